// round 10
// baseline (speedup 1.0000x reference)
#include <cuda_runtime.h>

#define THREADS 256
#define TT 30

typedef unsigned long long ull;

// ---------------- smem layout (float offsets) ----------------
// P1 weights (rows reordered to u*4+g, k-contiguous):
#define W1o 0        // [256][80]  = 20480
#define W2o 20480    // [128][96]  = 12288  (ends 32768)
// P2 overlay:
#define W3o 0        // [128][32]  = 4096
#define W4o 4096     // [256][96]  = 24576
#define WI3o 28672   // [128][32]  = 4096
#define WOo 32768    // [16][68]   = 1088   (ends 33856)
// biases (interleaved [u][g]):
#define B1o 33856
#define B2o 34112
#define B3o 34240
#define B4o 34368
#define BOo 34624    // 16 (ends 34640)
// state [row][k], k-contiguous, XOR-chunk swizzled, double buffered:
#define XINo 34640   // 2*[32][16] = 1024
#define H1o  35664   // 2*[32][64] = 4096   (P2: h4)
#define H2o  39760   // 2*[32][32] = 2048   (P2: h3)
#define SHF  41808   // 167232 bytes

__device__ __forceinline__ void ffma2(ull &acc, ull a, ull b){
    asm("fma.rn.f32x2 %0, %1, %2, %0;" : "+l"(acc) : "l"(a), "l"(b));
}
__device__ __forceinline__ ull pack2(float x, float y){
    ull r; asm("mov.b64 %0, {%1, %2};" : "=l"(r) : "f"(x), "f"(y)); return r;
}
__device__ __forceinline__ float2 unpack2(ull v){
    float2 f; asm("mov.b64 {%0, %1}, %2;" : "=f"(f.x), "=f"(f.y) : "l"(v)); return f;
}
__device__ __forceinline__ float ex2x(float x){
    float e; asm("ex2.approx.f32 %0, %1;" : "=f"(e) : "f"(x)); return e;
}
__device__ __forceinline__ float rcpx(float x){
    float r; asm("rcp.approx.f32 %0, %1;" : "=f"(r) : "f"(x)); return r;
}

// 8-MUFU LSTM activation (gate order i,f,g,o). Returns h, updates c.
__device__ __forceinline__ float act8(float zi, float zf, float zg, float zo, float &c){
    const float K1 = -1.4426950408889634f;
    float ei = ex2x(K1 * zi);
    float ef = ex2x(K1 * zf);
    float eg = ex2x(2.0f * K1 * zg);
    float eo = ex2x(K1 * zo);
    float A = 1.0f + ei, F = 1.0f + ef, G = 1.0f + eg, O = 1.0f + eo;
    float it = (1.0f - eg) * rcpx(A * G);
    float cn = fmaf(c, rcpx(F), it);
    float ec = ex2x(2.0f * K1 * cn);
    float C = 1.0f + ec;
    c = cn;
    return (1.0f - ec) * rcpx(O * C);
}

// k-pair packed accumulation.
// acc[j][g][i] is an f32x2 accumulating k-pairs for unit u0+j, gate g, row r0+i.
// inb: state base pre-offset by r0*ST; chunks XOR-swizzled by s (the rows' r>>2).
// Wb:  weight base pre-offset to row (u0*4), stride WST, k-contiguous (no swizzle).
template<int NU, int NKQ>
__device__ __forceinline__ void accum(const float* __restrict__ inb, int ST, int s,
                                      const float* __restrict__ Wb, int WST,
                                      ull (&acc)[NU][4][4])
{
#pragma unroll 4
    for (int kq = 0; kq < NKQ; kq++) {
        const float* ib = inb + 4 * (kq ^ s);
        ulonglong2 h0 = *reinterpret_cast<const ulonglong2*>(ib);
        ulonglong2 h1 = *reinterpret_cast<const ulonglong2*>(ib + ST);
        ulonglong2 h2 = *reinterpret_cast<const ulonglong2*>(ib + 2 * ST);
        ulonglong2 h3 = *reinterpret_cast<const ulonglong2*>(ib + 3 * ST);
#pragma unroll
        for (int j = 0; j < NU; j++)
#pragma unroll
            for (int g = 0; g < 4; g++) {
                ulonglong2 wv = *reinterpret_cast<const ulonglong2*>(Wb + (j*4+g)*WST + 4*kq);
                ffma2(acc[j][g][0], wv.x, h0.x); ffma2(acc[j][g][0], wv.y, h0.y);
                ffma2(acc[j][g][1], wv.x, h1.x); ffma2(acc[j][g][1], wv.y, h1.y);
                ffma2(acc[j][g][2], wv.x, h2.x); ffma2(acc[j][g][2], wv.y, h2.y);
                ffma2(acc[j][g][3], wv.x, h3.x); ffma2(acc[j][g][3], wv.y, h3.y);
            }
    }
}

template<int NU>
__device__ __forceinline__ void init_acc(ull (&acc)[NU][4][4], const float (&b)[NU][4]){
#pragma unroll
    for (int j = 0; j < NU; j++)
#pragma unroll
        for (int g = 0; g < 4; g++) {
            ull bp = pack2(b[j][g], 0.0f);
#pragma unroll
            for (int i = 0; i < 4; i++) acc[j][g][i] = bp;
        }
}

// fold k-pairs (lo+hi), activate, store h scalars into [row][k=unit] swizzled layout.
// hb pre-offset by r0*ST; s = rows' swizzle.
template<int NU>
__device__ __forceinline__ void act_store(ull (&acc)[NU][4][4], float (&c)[NU][4],
                                          float* hb, int ST, int s, int u0)
{
#pragma unroll
    for (int j = 0; j < NU; j++) {
        int u = u0 + j;
        float* col = hb + 4 * ((u >> 2) ^ s) + (u & 3);
#pragma unroll
        for (int i = 0; i < 4; i++) {
            float2 a0 = unpack2(acc[j][0][i]);
            float2 a1 = unpack2(acc[j][1][i]);
            float2 a2 = unpack2(acc[j][2][i]);
            float2 a3 = unpack2(acc[j][3][i]);
            float h = act8(a0.x + a0.y, a1.x + a1.y, a2.x + a2.y, a3.x + a3.y, c[j][i]);
            col[i * ST] = h;
        }
    }
}

__global__ void __launch_bounds__(THREADS, 1)
lstm_ae(const float* __restrict__ x,
        const float* __restrict__ Wih1, const float* __restrict__ Whh1, const float* __restrict__ b1,
        const float* __restrict__ Wih2, const float* __restrict__ Whh2, const float* __restrict__ b2,
        const float* __restrict__ Wih3, const float* __restrict__ Whh3, const float* __restrict__ b3,
        const float* __restrict__ Wih4, const float* __restrict__ Whh4, const float* __restrict__ b4,
        const float* __restrict__ Wout, const float* __restrict__ bout,
        float* __restrict__ out)
{
    extern __shared__ float sh[];
    const int tid = threadIdx.x;
    const long row0 = (long)blockIdx.x * 32;

    const int ug  = tid >> 3;              // 0..31
    const int r0  = (tid & 7) * 4;         // 4 rows per thread
    const int sw  = tid & 7;               // = r>>2 for all 4 rows
    const int swx = sw & 3;                // XIN (4 chunks)
    const int u0a = ug * 2;                // H=64 layers: 2 units
    const int u0b = ug;                    // H=32 layers: 1 unit

    // projection / x-io mapping: 1 row, features f and f+8
    const int xr = tid >> 3;
    const int xf = tid & 7;
    const int sxw = (xr >> 2) & 3;         // XIN writer swizzle
    const int sp  = (xr >> 2) & 7;         // h4 reader swizzle

    // ---- P1 weights (rows u*4+g, k-contiguous) + biases ----
    for (int i = tid; i < 256 * 80; i += THREADS) {
        int row = i / 80, k = i - row * 80;
        int u = row >> 2, g = row & 3;
        sh[W1o + i] = (k < 16) ? Wih1[(g * 64 + u) * 16 + k]
                               : Whh1[(g * 64 + u) * 64 + (k - 16)];
    }
    for (int i = tid; i < 128 * 96; i += THREADS) {
        int row = i / 96, k = i - row * 96;
        int u = row >> 2, g = row & 3;
        sh[W2o + i] = (k < 64) ? Wih2[(g * 32 + u) * 64 + k]
                               : Whh2[(g * 32 + u) * 32 + (k - 64)];
    }
    if (tid < 256) { int u = tid >> 2, g = tid & 3; sh[B1o + tid] = b1[g * 64 + u]; }
    if (tid < 128) { int u = tid >> 2, g = tid & 3; sh[B2o + tid] = b2[g * 32 + u]; }
    if (tid < 128) { int u = tid >> 2, g = tid & 3; sh[B3o + tid] = b3[g * 32 + u]; }
    if (tid < 256) { int u = tid >> 2, g = tid & 3; sh[B4o + tid] = b4[g * 64 + u]; }
    if (tid < 16)  sh[BOo + tid] = bout[tid];
    for (int i = tid; i < 2048; i += THREADS) sh[H1o + i] = 0.f;  // h1 buf0
    for (int i = tid; i < 1024; i += THREADS) sh[H2o + i] = 0.f;  // h2 buf0
    {   // x(0) -> XIN buf0
        int xf0 = xf * 2;
        float2 gx = *reinterpret_cast<const float2*>(x + (row0 + xr) * (TT * 16) + xf0);
        float* dst = sh + XINo + xr * 16 + 4 * ((xf0 >> 2) ^ sxw) + (xf0 & 3);
        *reinterpret_cast<float2*>(dst) = gx;
    }
    __syncthreads();

    float bs1[2][4], bs2[1][4];
#pragma unroll
    for (int j = 0; j < 2; j++)
#pragma unroll
        for (int g = 0; g < 4; g++) bs1[j][g] = sh[B1o + (u0a + j) * 4 + g];
#pragma unroll
    for (int g = 0; g < 4; g++) bs2[0][g] = sh[B2o + u0b * 4 + g];

    float c1[2][4], c2[1][4];
#pragma unroll
    for (int j = 0; j < 2; j++)
#pragma unroll
        for (int i = 0; i < 4; i++) c1[j][i] = 0.f;
#pragma unroll
    for (int i = 0; i < 4; i++) c2[0][i] = 0.f;

    // ---- phase 1: encoder LSTM(64) -> LSTM(32) ----
    for (int t = 0; t < TT; t++) {
        const int p = t & 1;
        float2 gx;
        const bool pf = (t + 1 < TT);
        if (pf) gx = *reinterpret_cast<const float2*>(
            x + (row0 + xr) * (TT * 16) + (t + 1) * 16 + xf * 2);
        {   // L1
            ull a1[2][4][4];
            init_acc<2>(a1, bs1);
            accum<2, 4>(sh + XINo + p * 512 + r0 * 16, 16, swx,
                        sh + W1o + (u0a * 4) * 80, 80, a1);
            accum<2, 16>(sh + H1o + p * 2048 + r0 * 64, 64, sw,
                         sh + W1o + (u0a * 4) * 80 + 16, 80, a1);
            if (pf) {
                int xf0 = xf * 2;
                float* dst = sh + XINo + (p ^ 1) * 512 + xr * 16
                           + 4 * ((xf0 >> 2) ^ sxw) + (xf0 & 3);
                *reinterpret_cast<float2*>(dst) = gx;
            }
            act_store<2>(a1, c1, sh + H1o + (p ^ 1) * 2048 + r0 * 64, 64, sw, u0a);
        }
        __syncthreads();
        {   // L2
            ull a2[1][4][4];
            init_acc<1>(a2, bs2);
            accum<1, 16>(sh + H1o + (p ^ 1) * 2048 + r0 * 64, 64, sw,
                         sh + W2o + (u0b * 4) * 96, 96, a2);
            accum<1, 8>(sh + H2o + p * 1024 + r0 * 32, 32, sw,
                        sh + W2o + (u0b * 4) * 96 + 64, 96, a2);
            act_store<1>(a2, c2, sh + H2o + (p ^ 1) * 1024 + r0 * 32, 32, sw, u0b);
        }
        __syncthreads();
    }
    // latent = h2(29) in H2 buf 0

    // ---- P2 weights (overlay) ----
    for (int i = tid; i < 128 * 32; i += THREADS) {
        int row = i >> 5, k = i & 31;
        int u = row >> 2, g = row & 3;
        sh[W3o + i] = Whh3[(g * 32 + u) * 32 + k];
    }
    for (int i = tid; i < 256 * 96; i += THREADS) {
        int row = i / 96, k = i - row * 96;
        int u = row >> 2, g = row & 3;
        sh[W4o + i] = (k < 32) ? Wih4[(g * 64 + u) * 32 + k]
                               : Whh4[(g * 64 + u) * 64 + (k - 32)];
    }
    for (int i = tid; i < 128 * 32; i += THREADS) {
        int row = i >> 5, k = i & 31;
        int u = row >> 2, g = row & 3;
        sh[WI3o + i] = Wih3[(g * 32 + u) * 32 + k];
    }
    for (int i = tid; i < 16 * 68; i += THREADS) {
        int f = i / 68, j = i - f * 68;
        sh[WOo + i] = (j < 64) ? Wout[f * 64 + j] : 0.f;
    }
    __syncthreads();

    // zin3 = Wih3 @ latent + b3 (constant over t), in registers
    ull z3[1][4][4];
    {
        float bs3[1][4];
#pragma unroll
        for (int g = 0; g < 4; g++) bs3[0][g] = sh[B3o + u0b * 4 + g];
        init_acc<1>(z3, bs3);
        accum<1, 8>(sh + H2o + r0 * 32, 32, sw, sh + WI3o + (u0b * 4) * 32, 32, z3);
    }
    __syncthreads();
    for (int i = tid; i < 1024; i += THREADS) sh[H2o + i] = 0.f;  // h3 buf0
    for (int i = tid; i < 2048; i += THREADS) sh[H1o + i] = 0.f;  // h4 buf0
    __syncthreads();

    float bs4[2][4];
#pragma unroll
    for (int j = 0; j < 2; j++)
#pragma unroll
        for (int g = 0; g < 4; g++) bs4[j][g] = sh[B4o + (u0a + j) * 4 + g];
    const ull bo1 = pack2(sh[BOo + xf], 0.0f);
    const ull bo2 = pack2(sh[BOo + xf + 8], 0.0f);

    float c3[1][4], c4[2][4];
#pragma unroll
    for (int i = 0; i < 4; i++) c3[0][i] = 0.f;
#pragma unroll
    for (int j = 0; j < 2; j++)
#pragma unroll
        for (int i = 0; i < 4; i++) c4[j][i] = 0.f;

    // ---- phase 2: decoder LSTM(32) -> LSTM(64) -> projection ----
    for (int t = 0; t < TT; t++) {
        const int p = t & 1;
        if (t > 0) {   // projection of h4(t-1) from H1[p]
            const float* hb = sh + H1o + p * 2048 + xr * 64;
            ull a0 = bo1, a1 = bo2;
#pragma unroll 4
            for (int kq = 0; kq < 16; kq++) {
                ulonglong2 hv = *reinterpret_cast<const ulonglong2*>(hb + 4 * (kq ^ sp));
                ulonglong2 w0 = *reinterpret_cast<const ulonglong2*>(sh + WOo + xf * 68 + 4 * kq);
                ulonglong2 w1 = *reinterpret_cast<const ulonglong2*>(sh + WOo + (xf + 8) * 68 + 4 * kq);
                ffma2(a0, w0.x, hv.x); ffma2(a0, w0.y, hv.y);
                ffma2(a1, w1.x, hv.x); ffma2(a1, w1.y, hv.y);
            }
            float2 y0 = unpack2(a0), y1 = unpack2(a1);
            float* op = out + (row0 + xr) * (TT * 16) + (t - 1) * 16;
            op[xf]     = y0.x + y0.y;
            op[xf + 8] = y1.x + y1.y;
        }
        {   // L3 (ih-part constant, lives in z3)
            ull a3[1][4][4];
#pragma unroll
            for (int g = 0; g < 4; g++)
#pragma unroll
                for (int i = 0; i < 4; i++) a3[0][g][i] = z3[0][g][i];
            accum<1, 8>(sh + H2o + p * 1024 + r0 * 32, 32, sw,
                        sh + W3o + (u0b * 4) * 32, 32, a3);
            act_store<1>(a3, c3, sh + H2o + (p ^ 1) * 1024 + r0 * 32, 32, sw, u0b);
        }
        __syncthreads();
        {   // L4
            ull a4[2][4][4];
            init_acc<2>(a4, bs4);
            accum<2, 8>(sh + H2o + (p ^ 1) * 1024 + r0 * 32, 32, sw,
                        sh + W4o + (u0a * 4) * 96, 96, a4);
            accum<2, 16>(sh + H1o + p * 2048 + r0 * 64, 64, sw,
                         sh + W4o + (u0a * 4) * 96 + 32, 96, a4);
            act_store<2>(a4, c4, sh + H1o + (p ^ 1) * 2048 + r0 * 64, 64, sw, u0a);
        }
        __syncthreads();
    }
    // final projection: h4(29) in H1 buf 0
    {
        const float* hb = sh + H1o + xr * 64;
        ull a0 = bo1, a1 = bo2;
#pragma unroll 4
        for (int kq = 0; kq < 16; kq++) {
            ulonglong2 hv = *reinterpret_cast<const ulonglong2*>(hb + 4 * (kq ^ sp));
            ulonglong2 w0 = *reinterpret_cast<const ulonglong2*>(sh + WOo + xf * 68 + 4 * kq);
            ulonglong2 w1 = *reinterpret_cast<const ulonglong2*>(sh + WOo + (xf + 8) * 68 + 4 * kq);
            ffma2(a0, w0.x, hv.x); ffma2(a0, w0.y, hv.y);
            ffma2(a1, w1.x, hv.x); ffma2(a1, w1.y, hv.y);
        }
        float2 y0 = unpack2(a0), y1 = unpack2(a1);
        float* op = out + (row0 + xr) * (TT * 16) + (TT - 1) * 16;
        op[xf]     = y0.x + y0.y;
        op[xf + 8] = y1.x + y1.y;
    }
}

extern "C" void kernel_launch(void* const* d_in, const int* in_sizes, int n_in,
                              void* d_out, int out_size)
{
    const float* x    = (const float*)d_in[0];
    const float* Wih1 = (const float*)d_in[1];
    const float* Whh1 = (const float*)d_in[2];
    const float* b1   = (const float*)d_in[3];
    const float* Wih2 = (const float*)d_in[4];
    const float* Whh2 = (const float*)d_in[5];
    const float* b2   = (const float*)d_in[6];
    const float* Wih3 = (const float*)d_in[7];
    const float* Whh3 = (const float*)d_in[8];
    const float* b3   = (const float*)d_in[9];
    const float* Wih4 = (const float*)d_in[10];
    const float* Whh4 = (const float*)d_in[11];
    const float* b4   = (const float*)d_in[12];
    const float* Wout = (const float*)d_in[13];
    const float* bout = (const float*)d_in[14];
    float* out = (float*)d_out;

    cudaFuncSetAttribute(lstm_ae, cudaFuncAttributeMaxDynamicSharedMemorySize,
                         SHF * (int)sizeof(float));
    lstm_ae<<<256, THREADS, SHF * sizeof(float)>>>(
        x, Wih1, Whh1, b1, Wih2, Whh2, b2, Wih3, Whh3, b3,
        Wih4, Whh4, b4, Wout, bout, out);
}

// round 11
// speedup vs baseline: 1.2247x; 1.2247x over previous
#include <cuda_runtime.h>

#define THREADS 256
#define TT 30
#define RS 68   // row stride (swizzle padding)

typedef unsigned long long ull;

// ---------------- global weight scratch (reordered by prep kernel) ----------------
// [k][u][g] interleaved per layer, float4-aligned quads per (u-pair, gate)
#define OW1  0        // [80][256]  = 20480
#define OW2  20480    // [96][128]  = 12288
#define OW3  32768    // [32][128]  = 4096   (Whh3)
#define OWI3 36864    // [32][128]  = 4096   (Wih3)
#define OW4  40960    // [96][256]  = 24576  -> total 65536
__device__ __align__(128) float g_w[65536];

// ---------------- shared memory layout (float offsets) ----------------
#define B1o    0      // 256  (interleaved [u][g])
#define B2o    256    // 128
#define B3o    384    // 128
#define B4o    512    // 256
#define BOo    768    // 16
#define WOUTo  784    // [64][16] = 1024
// state [k][row] stride RS, rows swizzled: phys(r) = r + 4*(r>=32)
#define XINo   1808   // 2 x [16][68] = 2176
#define H1o    3984   // 2 x [64][68] = 8704   (P2: h4)
#define H2o    12688  // 2 x [32][68] = 4352   (P2: h3)
#define SHF    17040  // 68160 bytes

__device__ __forceinline__ void ffma2(ull &acc, ull a, ull b){
    asm("fma.rn.f32x2 %0, %1, %2, %0;" : "+l"(acc) : "l"(a), "l"(b));
}
__device__ __forceinline__ ull bcast2(float w){
    ull r; asm("mov.b64 %0, {%1, %1};" : "=l"(r) : "f"(w)); return r;
}
__device__ __forceinline__ ull pack2(float x, float y){
    ull r; asm("mov.b64 %0, {%1, %2};" : "=l"(r) : "f"(x), "f"(y)); return r;
}
__device__ __forceinline__ float2 unpack2(ull v){
    float2 f; asm("mov.b64 {%0, %1}, %2;" : "=f"(f.x), "=f"(f.y) : "l"(v)); return f;
}
__device__ __forceinline__ float ex2x(float x){
    float e; asm("ex2.approx.f32 %0, %1;" : "=f"(e) : "f"(x)); return e;
}
__device__ __forceinline__ float rcpx(float x){
    float r; asm("rcp.approx.f32 %0, %1;" : "=f"(r) : "f"(x)); return r;
}

// 8-MUFU LSTM activation (gate order i,f,g,o). Returns h, updates c.
__device__ __forceinline__ float act8(float zi, float zf, float zg, float zo, float &c){
    const float K1 = -1.4426950408889634f;
    float ei = ex2x(K1 * zi);
    float ef = ex2x(K1 * zf);
    float eg = ex2x(2.0f * K1 * zg);
    float eo = ex2x(K1 * zo);
    float A = 1.0f + ei, F = 1.0f + ef, G = 1.0f + eg, O = 1.0f + eo;
    float it = (1.0f - eg) * rcpx(A * G);
    float cn = fmaf(c, rcpx(F), it);
    float ec = ex2x(2.0f * K1 * cn);
    float C = 1.0f + ec;
    c = cn;
    return (1.0f - ec) * rcpx(O * C);
}

// acc[j][g][p] += sum_k W[k][u][g] * in[k][pr0+2p..]
// in: SHARED [k][row] stride RS; W: GLOBAL (L1-cached, warp-uniform quads)
template<int NU, int NG>
__device__ __forceinline__ void accum(const float* __restrict__ in,
                                      const float* __restrict__ W,
                                      int K, ull (&acc)[NU][4][4], int pr0)
{
#pragma unroll 4
    for (int k = 0; k < K; k++) {
        ulonglong2 hA = *reinterpret_cast<const ulonglong2*>(in + k*RS + pr0);
        ulonglong2 hB = *reinterpret_cast<const ulonglong2*>(in + k*RS + pr0 + 4);
        ull hp0 = hA.x, hp1 = hA.y, hp2 = hB.x, hp3 = hB.y;
#pragma unroll
        for (int j = 0; j < NU; j++) {
            float4 w = __ldg(reinterpret_cast<const float4*>(W + k*NG + j*4));
            ull w0 = bcast2(w.x), w1 = bcast2(w.y), w2 = bcast2(w.z), w3 = bcast2(w.w);
            ffma2(acc[j][0][0], w0, hp0); ffma2(acc[j][0][1], w0, hp1);
            ffma2(acc[j][0][2], w0, hp2); ffma2(acc[j][0][3], w0, hp3);
            ffma2(acc[j][1][0], w1, hp0); ffma2(acc[j][1][1], w1, hp1);
            ffma2(acc[j][1][2], w1, hp2); ffma2(acc[j][1][3], w1, hp3);
            ffma2(acc[j][2][0], w2, hp0); ffma2(acc[j][2][1], w2, hp1);
            ffma2(acc[j][2][2], w2, hp2); ffma2(acc[j][2][3], w2, hp3);
            ffma2(acc[j][3][0], w3, hp0); ffma2(acc[j][3][1], w3, hp1);
            ffma2(acc[j][3][2], w3, hp2); ffma2(acc[j][3][3], w3, hp3);
        }
    }
}

template<int NU>
__device__ __forceinline__ void init_acc(ull (&acc)[NU][4][4], const ull (&b)[NU][4]){
#pragma unroll
    for (int j = 0; j < NU; j++)
#pragma unroll
        for (int g = 0; g < 4; g++)
#pragma unroll
            for (int p = 0; p < 4; p++) acc[j][g][p] = b[j][g];
}

template<int NU>
__device__ __forceinline__ void act_store(ull (&acc)[NU][4][4], float (&c)[NU][8],
                                          float* hdst, int pr0)
{
#pragma unroll
    for (int j = 0; j < NU; j++)
#pragma unroll
    for (int p = 0; p < 4; p++) {
        float2 zi = unpack2(acc[j][0][p]);
        float2 zf = unpack2(acc[j][1][p]);
        float2 zg = unpack2(acc[j][2][p]);
        float2 zo = unpack2(acc[j][3][p]);
        float h0 = act8(zi.x, zf.x, zg.x, zo.x, c[j][2*p]);
        float h1 = act8(zi.y, zf.y, zg.y, zo.y, c[j][2*p+1]);
        *reinterpret_cast<ull*>(hdst + j*RS + pr0 + 2*p) = pack2(h0, h1);
    }
}

// -------- prep kernel: reorder weights into g_w ([k][u][g] interleaved) --------
__global__ void prep_w(const float* __restrict__ Wih1, const float* __restrict__ Whh1,
                       const float* __restrict__ Wih2, const float* __restrict__ Whh2,
                       const float* __restrict__ Wih3, const float* __restrict__ Whh3,
                       const float* __restrict__ Wih4, const float* __restrict__ Whh4)
{
    int i = blockIdx.x * blockDim.x + threadIdx.x;
    if (i < 20480) {                              // W1: [80][256]
        int k = i >> 8, j = i & 255, u = j >> 2, g = j & 3;
        g_w[OW1 + i] = (k < 16) ? Wih1[(g * 64 + u) * 16 + k]
                                : Whh1[(g * 64 + u) * 64 + (k - 16)];
    } else if (i < 32768) {                       // W2: [96][128]
        int q = i - 20480;
        int k = q >> 7, j = q & 127, u = j >> 2, g = j & 3;
        g_w[OW2 + q] = (k < 64) ? Wih2[(g * 32 + u) * 64 + k]
                                : Whh2[(g * 32 + u) * 32 + (k - 64)];
    } else if (i < 36864) {                       // W3hh: [32][128]
        int q = i - 32768;
        int k = q >> 7, j = q & 127, u = j >> 2, g = j & 3;
        g_w[OW3 + q] = Whh3[(g * 32 + u) * 32 + k];
    } else if (i < 40960) {                       // Wih3: [32][128]
        int q = i - 36864;
        int k = q >> 7, j = q & 127, u = j >> 2, g = j & 3;
        g_w[OWI3 + q] = Wih3[(g * 32 + u) * 32 + k];
    } else if (i < 65536) {                       // W4: [96][256]
        int q = i - 40960;
        int k = q >> 8, j = q & 255, u = j >> 2, g = j & 3;
        g_w[OW4 + q] = (k < 32) ? Wih4[(g * 64 + u) * 32 + k]
                                : Whh4[(g * 64 + u) * 64 + (k - 32)];
    }
}

__global__ void __launch_bounds__(THREADS, 1)
lstm_ae(const float* __restrict__ x,
        const float* __restrict__ b1, const float* __restrict__ b2,
        const float* __restrict__ b3, const float* __restrict__ b4,
        const float* __restrict__ Wout, const float* __restrict__ bout,
        float* __restrict__ out)
{
    extern __shared__ float sh[];
    const int tid = threadIdx.x;
    const int wid = tid >> 5;
    const bool grpA = ((wid >> 2) & 1) == 0;  // SMSP pairs (w, w+4) differ
    const long row0 = (long)blockIdx.x * 64;

    const int u0a = (tid >> 3) * 2;
    const int u0b = (tid >> 3);
    const int r0  = (tid & 7) * 8;
    const int pr0 = r0 + ((r0 & 32) >> 3);

    const float* gW1  = g_w + OW1;
    const float* gW2  = g_w + OW2;
    const float* gW3  = g_w + OW3;
    const float* gWI3 = g_w + OWI3;
    const float* gW4  = g_w + OW4;

    // ---- biases + Wout staging, zero state ----
    if (tid < 256) { int u = tid >> 2, g = tid & 3; sh[B1o + tid] = b1[g * 64 + u]; }
    if (tid < 128) { int u = tid >> 2, g = tid & 3; sh[B2o + tid] = b2[g * 32 + u]; }
    if (tid < 128) { int u = tid >> 2, g = tid & 3; sh[B3o + tid] = b3[g * 32 + u]; }
    if (tid < 256) { int u = tid >> 2, g = tid & 3; sh[B4o + tid] = b4[g * 64 + u]; }
    if (tid < 16)  sh[BOo + tid] = bout[tid];
    for (int i = tid; i < 1024; i += THREADS) {
        int jr = i >> 4, f = i & 15;
        sh[WOUTo + i] = Wout[f * 64 + jr];
    }
    for (int i = tid; i < 4352; i += THREADS) sh[H1o + i] = 0.f;   // h1 buf0
    for (int i = tid; i < 2176; i += THREADS) sh[H2o + i] = 0.f;   // h2 buf0
    {
        int f0 = (tid & 3) * 4, r = tid >> 2;
        int pr = r + ((r & 32) >> 3);
        float4 gx = __ldcs(reinterpret_cast<const float4*>(x + (row0 + r) * (TT * 16) + f0));
        sh[XINo + (f0 + 0) * RS + pr] = gx.x;
        sh[XINo + (f0 + 1) * RS + pr] = gx.y;
        sh[XINo + (f0 + 2) * RS + pr] = gx.z;
        sh[XINo + (f0 + 3) * RS + pr] = gx.w;
    }
    __syncthreads();

    ull b1p[2][4], b2p[1][4];
#pragma unroll
    for (int j = 0; j < 2; j++)
#pragma unroll
        for (int g = 0; g < 4; g++) b1p[j][g] = bcast2(sh[B1o + (u0a + j) * 4 + g]);
#pragma unroll
    for (int g = 0; g < 4; g++) b2p[0][g] = bcast2(sh[B2o + u0b * 4 + g]);

    float c1[2][8], c2[1][8];
#pragma unroll
    for (int j = 0; j < 2; j++)
#pragma unroll
        for (int q = 0; q < 8; q++) c1[j][q] = 0.f;
#pragma unroll
    for (int q = 0; q < 8; q++) c2[0][q] = 0.f;

    // ---- phase 1: encoder. accL1 enters each t as b1 + Whh1@h1(t-1). ----
    ull accL1[2][4][4], accL2[1][4][4];
    init_acc<2>(accL1, b1p);                 // h1(-1) = 0

    for (int t = 0; t < TT; t++) {
        const int p = t & 1;
        float4 gx;
        const bool pf = (t + 1 < TT);
        if (pf) gx = __ldcs(reinterpret_cast<const float4*>(
            x + (row0 + (tid >> 2)) * (TT * 16) + (t + 1) * 16 + (tid & 3) * 4));
        accum<2, 256>(sh + XINo + p * (16 * RS), gW1 + u0a * 4, 16, accL1, pr0);
        if (pf) {
            int f0 = (tid & 3) * 4, r = tid >> 2;
            int pr = r + ((r & 32) >> 3);
            float* xb = sh + XINo + (p ^ 1) * (16 * RS);
            xb[(f0 + 0) * RS + pr] = gx.x;
            xb[(f0 + 1) * RS + pr] = gx.y;
            xb[(f0 + 2) * RS + pr] = gx.z;
            xb[(f0 + 3) * RS + pr] = gx.w;
        }
        if (grpA) {
            act_store<2>(accL1, c1, sh + H1o + (p ^ 1) * (64 * RS) + u0a * RS, pr0);
            init_acc<1>(accL2, b2p);
            accum<1, 128>(sh + H2o + p * (32 * RS), gW2 + 64 * 128 + u0b * 4, 32, accL2, pr0);
        } else {
            init_acc<1>(accL2, b2p);
            accum<1, 128>(sh + H2o + p * (32 * RS), gW2 + 64 * 128 + u0b * 4, 32, accL2, pr0);
            act_store<2>(accL1, c1, sh + H1o + (p ^ 1) * (64 * RS) + u0a * RS, pr0);
        }
        __syncthreads();
        accum<1, 128>(sh + H1o + (p ^ 1) * (64 * RS), gW2 + u0b * 4, 64, accL2, pr0);
        if (grpA) {
            act_store<1>(accL2, c2, sh + H2o + (p ^ 1) * (32 * RS) + u0b * RS, pr0);
            init_acc<2>(accL1, b1p);
            accum<2, 256>(sh + H1o + (p ^ 1) * (64 * RS), gW1 + 16 * 256 + u0a * 4, 64, accL1, pr0);
        } else {
            init_acc<2>(accL1, b1p);
            accum<2, 256>(sh + H1o + (p ^ 1) * (64 * RS), gW1 + 16 * 256 + u0a * 4, 64, accL1, pr0);
            act_store<1>(accL2, c2, sh + H2o + (p ^ 1) * (32 * RS) + u0b * RS, pr0);
        }
        __syncthreads();
    }
    // latent = h2(29) in H2 buf 0

    // zin3 = Wih3 @ latent + b3 (constant over t), in registers
    ull zin3[1][4][4];
    {
        ull b3p[1][4];
#pragma unroll
        for (int g = 0; g < 4; g++) b3p[0][g] = bcast2(sh[B3o + u0b * 4 + g]);
        init_acc<1>(zin3, b3p);
        accum<1, 128>(sh + H2o, gWI3 + u0b * 4, 32, zin3, pr0);
        __syncthreads();   // latent reads done before H2 reuse as h3
        for (int i = tid; i < 2176; i += THREADS) sh[H2o + i] = 0.f;  // h3 buf0
        for (int i = tid; i < 4352; i += THREADS) sh[H1o + i] = 0.f;  // h4 buf0
    }
    __syncthreads();

    ull b4p[2][4];
#pragma unroll
    for (int j = 0; j < 2; j++)
#pragma unroll
        for (int g = 0; g < 4; g++) b4p[j][g] = bcast2(sh[B4o + (u0a + j) * 4 + g]);
    const float boutf = sh[BOo + (tid & 15)];
    const int fo = tid & 15, rb = tid >> 4;
    const int prb = rb * 4 + ((rb & 8) >> 1);

    float c3[1][8], c4[2][8];
#pragma unroll
    for (int q = 0; q < 8; q++) c3[0][q] = 0.f;
#pragma unroll
    for (int j = 0; j < 2; j++)
#pragma unroll
        for (int q = 0; q < 8; q++) c4[j][q] = 0.f;

    // ---- phase 2: decoder. accL3 enters each t as zin3 + Whh3@h3(t-1). ----
    ull accL3[1][4][4], accL4[2][4][4];
#pragma unroll
    for (int g = 0; g < 4; g++)
#pragma unroll
        for (int pp = 0; pp < 4; pp++) accL3[0][g][pp] = zin3[0][g][pp];  // h3(-1)=0

    for (int t = 0; t < TT; t++) {
        const int p = t & 1;
        if (grpA) {
            act_store<1>(accL3, c3, sh + H2o + (p ^ 1) * (32 * RS) + u0b * RS, pr0);
            init_acc<2>(accL4, b4p);
            accum<2, 256>(sh + H1o + p * (64 * RS), gW4 + 32 * 256 + u0a * 4, 64, accL4, pr0);
        } else {
            init_acc<2>(accL4, b4p);
            accum<2, 256>(sh + H1o + p * (64 * RS), gW4 + 32 * 256 + u0a * 4, 64, accL4, pr0);
        }
        if (t > 0) {   // projection of h4(t-1), overlapped
            const float* h4 = sh + H1o + p * (64 * RS);
            ull a0 = bcast2(boutf), a1 = a0;
#pragma unroll 8
            for (int j = 0; j < 64; j++) {
                ull w = bcast2(sh[WOUTo + j * 16 + fo]);
                ull hq0 = *reinterpret_cast<const ull*>(h4 + j * RS + prb);
                ull hq1 = *reinterpret_cast<const ull*>(h4 + j * RS + prb + 2);
                ffma2(a0, w, hq0);
                ffma2(a1, w, hq1);
            }
            float2 y01 = unpack2(a0), y23 = unpack2(a1);
            long ob = (row0 + rb * 4) * (TT * 16) + (t - 1) * 16 + fo;
            out[ob]               = y01.x;
            out[ob + TT * 16]     = y01.y;
            out[ob + 2 * TT * 16] = y23.x;
            out[ob + 3 * TT * 16] = y23.y;
        }
        if (!grpA)
            act_store<1>(accL3, c3, sh + H2o + (p ^ 1) * (32 * RS) + u0b * RS, pr0);
        __syncthreads();
        accum<2, 256>(sh + H2o + (p ^ 1) * (32 * RS), gW4 + u0a * 4, 32, accL4, pr0);
        if (grpA) {
            act_store<2>(accL4, c4, sh + H1o + (p ^ 1) * (64 * RS) + u0a * RS, pr0);
#pragma unroll
            for (int g = 0; g < 4; g++)
#pragma unroll
                for (int pp = 0; pp < 4; pp++) accL3[0][g][pp] = zin3[0][g][pp];
            accum<1, 128>(sh + H2o + (p ^ 1) * (32 * RS), gW3 + u0b * 4, 32, accL3, pr0);
        } else {
#pragma unroll
            for (int g = 0; g < 4; g++)
#pragma unroll
                for (int pp = 0; pp < 4; pp++) accL3[0][g][pp] = zin3[0][g][pp];
            accum<1, 128>(sh + H2o + (p ^ 1) * (32 * RS), gW3 + u0b * 4, 32, accL3, pr0);
            act_store<2>(accL4, c4, sh + H1o + (p ^ 1) * (64 * RS) + u0a * RS, pr0);
        }
        __syncthreads();
    }
    // final projection: h4(29) in H1 buf 0
    {
        const float* h4 = sh + H1o;
        ull a0 = bcast2(boutf), a1 = a0;
#pragma unroll 8
        for (int j = 0; j < 64; j++) {
            ull w = bcast2(sh[WOUTo + j * 16 + fo]);
            ull hq0 = *reinterpret_cast<const ull*>(h4 + j * RS + prb);
            ull hq1 = *reinterpret_cast<const ull*>(h4 + j * RS + prb + 2);
            ffma2(a0, w, hq0);
            ffma2(a1, w, hq1);
        }
        float2 y01 = unpack2(a0), y23 = unpack2(a1);
        long ob = (row0 + rb * 4) * (TT * 16) + (TT - 1) * 16 + fo;
        out[ob]               = y01.x;
        out[ob + TT * 16]     = y01.y;
        out[ob + 2 * TT * 16] = y23.x;
        out[ob + 3 * TT * 16] = y23.y;
    }
}

extern "C" void kernel_launch(void* const* d_in, const int* in_sizes, int n_in,
                              void* d_out, int out_size)
{
    const float* x    = (const float*)d_in[0];
    const float* Wih1 = (const float*)d_in[1];
    const float* Whh1 = (const float*)d_in[2];
    const float* b1   = (const float*)d_in[3];
    const float* Wih2 = (const float*)d_in[4];
    const float* Whh2 = (const float*)d_in[5];
    const float* b2   = (const float*)d_in[6];
    const float* Wih3 = (const float*)d_in[7];
    const float* Whh3 = (const float*)d_in[8];
    const float* b3   = (const float*)d_in[9];
    const float* Wih4 = (const float*)d_in[10];
    const float* Whh4 = (const float*)d_in[11];
    const float* b4   = (const float*)d_in[12];
    const float* Wout = (const float*)d_in[13];
    const float* bout = (const float*)d_in[14];
    float* out = (float*)d_out;

    prep_w<<<256, 256>>>(Wih1, Whh1, Wih2, Whh2, Wih3, Whh3, Wih4, Whh4);

    cudaFuncSetAttribute(lstm_ae, cudaFuncAttributeMaxDynamicSharedMemorySize,
                         SHF * (int)sizeof(float));
    lstm_ae<<<128, THREADS, SHF * sizeof(float)>>>(
        x, b1, b2, b3, b4, Wout, bout, out);
}